// round 8
// baseline (speedup 1.0000x reference)
#include <cuda_runtime.h>
#include <cuda_bf16.h>
#include <cstdint>

// Problem constants: B=8, S=2048, H=512, G=2, V=320, D=256
#define MM 16384      // B*S
#define KK 512        // H
#define NN 640        // G*V
#define VV 320
#define DG 128        // D/G

// ---------------------------------------------------------------------------
// Scratch (static device globals: allocation-free)
// ---------------------------------------------------------------------------
__device__ __nv_bfloat16 g_Ah[(size_t)MM * KK];             // hidden bf16 [M,K]
__device__ __nv_bfloat16 g_Wb[(size_t)KK * NN];             // W bf16 [K,N] (same layout)
__device__ float g_marginal[NN];
__device__ float g_maskf[MM];
__device__ float g_msum;

__device__ __forceinline__ uint32_t smem_u32(const void* p) {
    uint32_t a;
    asm("{ .reg .u64 t; cvta.to.shared.u64 t, %1; cvt.u32.u64 %0, t; }" : "=r"(a) : "l"(p));
    return a;
}
__device__ __forceinline__ void cp_async16(uint32_t saddr, const void* gaddr) {
    asm volatile("cp.async.cg.shared.global [%0], [%1], 16;" :: "r"(saddr), "l"(gaddr));
}
__device__ __forceinline__ void ldmatrix_x4(uint32_t* r, uint32_t addr) {
    asm volatile("ldmatrix.sync.aligned.m8n8.x4.shared.b16 {%0,%1,%2,%3}, [%4];"
                 : "=r"(r[0]), "=r"(r[1]), "=r"(r[2]), "=r"(r[3]) : "r"(addr));
}
__device__ __forceinline__ void ldmatrix_x4_trans(uint32_t* r, uint32_t addr) {
    asm volatile("ldmatrix.sync.aligned.m8n8.x4.trans.shared.b16 {%0,%1,%2,%3}, [%4];"
                 : "=r"(r[0]), "=r"(r[1]), "=r"(r[2]), "=r"(r[3]) : "r"(addr));
}
__device__ __forceinline__ void mma16816(float* c, const uint32_t* a, uint32_t b0, uint32_t b1) {
    asm volatile("mma.sync.aligned.m16n8k16.row.col.f32.bf16.bf16.f32 "
                 "{%0,%1,%2,%3}, {%4,%5,%6,%7}, {%8,%9}, {%0,%1,%2,%3};"
                 : "+f"(c[0]), "+f"(c[1]), "+f"(c[2]), "+f"(c[3])
                 : "r"(a[0]), "r"(a[1]), "r"(a[2]), "r"(a[3]), "r"(b0), "r"(b1));
}

// ---------------------------------------------------------------------------
// Fused pre-pass:
//   block 0        : init (zero marginal, mask detect/expand/sum)
//   blocks 1..80   : convert W fp32 [K,N] -> bf16 [K,N] (float4, coalesced)
//   blocks 81..2128: convert hidden fp32 -> bf16 (float4, coalesced)
// ---------------------------------------------------------------------------
#define W4_BLOCKS 80                  // NN*KK/4 / 1024
#define A4_BLOCKS 2048                // MM*KK/4 / 1024
#define PRE_GRID (1 + W4_BLOCKS + A4_BLOCKS)

__global__ void __launch_bounds__(1024) pre_kernel(const float* __restrict__ A,
                                                   const float* __restrict__ W,
                                                   const void* __restrict__ maskraw) {
    int bx = blockIdx.x;
    int tid = threadIdx.x;

    if (bx == 0) {
        if (tid < NN) g_marginal[tid] = 0.f;

        __shared__ int isU8;
        if (tid == 0) isU8 = 0;
        __syncthreads();

        const unsigned char* mb = (const unsigned char*)maskraw;
        int any = 0;
        for (int i = tid; i < MM; i += 1024)
            if ((i & 3) && mb[i]) any = 1;
        if (any) isU8 = 1;
        __syncthreads();

        bool u8 = (isU8 != 0);
        const int* mi = (const int*)maskraw;
        float local = 0.f;
        for (int i = tid; i < MM; i += 1024) {
            bool on = u8 ? (mb[i] != 0) : (mi[i] != 0);
            float v = on ? 1.f : 0.f;
            g_maskf[i] = v;
            local += v;
        }
        __shared__ float red[32];
        for (int o = 16; o; o >>= 1) local += __shfl_xor_sync(0xffffffffu, local, o);
        if ((tid & 31) == 0) red[tid >> 5] = local;
        __syncthreads();
        if (tid < 32) {
            float s = red[tid];
            for (int o = 16; o; o >>= 1) s += __shfl_xor_sync(0xffffffffu, s, o);
            if (tid == 0) g_msum = s;
        }
        return;
    }

    if (bx <= W4_BLOCKS) {
        size_t i4 = (size_t)(bx - 1) * 1024 + tid;             // over NN*KK/4
        float4 v = ((const float4*)W)[i4];
        __nv_bfloat162 h0, h1;
        h0.x = __float2bfloat16(v.x); h0.y = __float2bfloat16(v.y);
        h1.x = __float2bfloat16(v.z); h1.y = __float2bfloat16(v.w);
        ((uint2*)g_Wb)[i4] = make_uint2(*(uint32_t*)&h0, *(uint32_t*)&h1);
    } else {
        size_t i4 = (size_t)(bx - 1 - W4_BLOCKS) * 1024 + tid; // over MM*KK/4
        float4 v = ((const float4*)A)[i4];
        __nv_bfloat162 h0, h1;
        h0.x = __float2bfloat16(v.x); h0.y = __float2bfloat16(v.y);
        h1.x = __float2bfloat16(v.z); h1.y = __float2bfloat16(v.w);
        ((uint2*)g_Ah)[i4] = make_uint2(*(uint32_t*)&h0, *(uint32_t*)&h1);
    }
}

// ---------------------------------------------------------------------------
// Exact fp32 rescore of one candidate column (warp-cooperative)
// ---------------------------------------------------------------------------
__device__ __forceinline__ float exact_score(const float* __restrict__ hidden,
                                             const float* __restrict__ W,
                                             const float* __restrict__ bias,
                                             const float* __restrict__ grow,
                                             int n, int col, int v, int lane) {
    const float* hrow = hidden + (size_t)n * KK;
    float s = 0.f;
#pragma unroll 4
    for (int j = lane; j < KK; j += 32)
        s = fmaf(hrow[j], W[(size_t)j * NN + col], s);
    for (int o = 16; o; o >>= 1) s += __shfl_xor_sync(0xffffffffu, s, o);
    return s + bias[col] + grow[v];
}

// ---------------------------------------------------------------------------
// Fused GEMM + row kernel.
// Grid (256 M-tiles, 2 groups). CTA: 512 threads (16 warps, 4m x 4n),
// tile 64 x 320, BK=64, 3-stage cp.async ring, one barrier per chunk.
// Epilogue: acc+bias -> smem logits tile; per-row argmax(+gumbel) with exact
// fp32 rescore of near-ties, masked softmax marginal, codevector gather.
// ---------------------------------------------------------------------------
#define TM 64
#define TN 320
#define BKC 64
#define NCHUNK 8                       // KK / BKC
#define AROWB 144                      // A smem row pitch (72 bf16)
#define BROWB 656                      // B smem row pitch (328 bf16)
#define SB_OFF 9216                    // B offset within stage (A = 64*144)
#define STAGE_BYTES 51200              // 9216 + 64*656
#define FUSED_SMEM 153600              // 3 stages
#define ELSTR 328                      // epilogue logits row pitch (floats)
#define MARG_OFF 83968                 // 64*328*4 bytes; marginal after tile

#define RESCORE_GAP  2.0e-2f
#define RESCORE_WIN  2.4e-2f

__global__ void __launch_bounds__(512, 1) fused_kernel(const float* __restrict__ bias,
                                                       const float* __restrict__ gumbels,
                                                       const float* __restrict__ cb,
                                                       float* __restrict__ out,
                                                       const float* __restrict__ hidden,
                                                       const float* __restrict__ W) {
    extern __shared__ char smem[];
    uint32_t sbase = smem_u32(smem);

    int tid = threadIdx.x;
    int lane = tid & 31;
    int wid = tid >> 5;
    int wm = wid >> 2;                 // 0..3 (16 m-rows each)
    int wn = wid & 3;                  // 0..3 (80 n-cols each)
    int m0 = blockIdx.x * TM;
    int g  = blockIdx.y;

    float acc[10][4];
#pragma unroll
    for (int i = 0; i < 10; i++)
#pragma unroll
        for (int r = 0; r < 4; r++) acc[i][r] = 0.f;

    // Load slots (kc-independent)
    int rowA = tid >> 3, segA = tid & 7;          // A: 512 segs of 16B
    int rB[5], sB[5];
#pragma unroll
    for (int i = 0; i < 5; i++) {                  // B: 2560 segs of 16B
        int idx = tid + i * 512;
        rB[i] = idx / 40; sB[i] = idx % 40;
    }

#define LOAD_CHUNK(kc, st) do {                                               \
        int koff = (kc) * BKC;                                                \
        uint32_t sb = sbase + (st) * STAGE_BYTES;                             \
        cp_async16(sb + rowA * AROWB + segA * 16,                             \
                   g_Ah + (size_t)(m0 + rowA) * KK + koff + segA * 8);        \
        _Pragma("unroll")                                                     \
        for (int i = 0; i < 5; i++)                                           \
            cp_async16(sb + SB_OFF + rB[i] * BROWB + sB[i] * 16,              \
                       g_Wb + (size_t)(koff + rB[i]) * NN + g * VV + sB[i] * 8); \
    } while (0)

    LOAD_CHUNK(0, 0); asm volatile("cp.async.commit_group;");
    LOAD_CHUNK(1, 1); asm volatile("cp.async.commit_group;");

    // ldmatrix per-lane offsets within a stage
    uint32_t aoff = (uint32_t)((wm * 16 + (lane & 15)) * AROWB + (lane >> 4) * 16);
    uint32_t boff = (uint32_t)(SB_OFF + ((lane & 7) + ((lane >> 3) & 1) * 8) * BROWB
                               + (wn * 80 + (lane >> 4) * 8) * 2);

    for (int kc = 0; kc < NCHUNK; kc++) {
        asm volatile("cp.async.wait_group 1;");    // chunk kc resident
        __syncthreads();

        if (kc + 2 < NCHUNK) LOAD_CHUNK(kc + 2, (kc + 2) % 3);
        asm volatile("cp.async.commit_group;");    // always commit

        uint32_t stb = sbase + (kc % 3) * STAGE_BYTES;
#pragma unroll
        for (int kk = 0; kk < 4; kk++) {
            uint32_t afr[4];
            ldmatrix_x4(afr, stb + aoff + kk * 32);
#pragma unroll
            for (int nt = 0; nt < 5; nt++) {
                uint32_t bfr[4];
                ldmatrix_x4_trans(bfr, stb + boff + kk * 16 * BROWB + nt * 32);
                mma16816(acc[2 * nt],     afr, bfr[0], bfr[1]);
                mma16816(acc[2 * nt + 1], afr, bfr[2], bfr[3]);
            }
        }
    }
    __syncthreads();   // all MMAs done; stage smem now reusable

    // ---- Epilogue: acc + bias -> smem logits tile ----
    float* EL = (float*)smem;
    float* smarg = (float*)(smem + MARG_OFF);
    {
        int re = wm * 16 + (lane >> 2);
        int cbase = wn * 80 + (lane & 3) * 2;
#pragma unroll
        for (int nj = 0; nj < 10; nj++) {
            int col = cbase + nj * 8;
            float bx = __ldg(&bias[g * VV + col]);
            float by = __ldg(&bias[g * VV + col + 1]);
            EL[re * ELSTR + col]           = acc[nj][0] + bx;
            EL[re * ELSTR + col + 1]       = acc[nj][1] + by;
            EL[(re + 8) * ELSTR + col]     = acc[nj][2] + bx;
            EL[(re + 8) * ELSTR + col + 1] = acc[nj][3] + by;
        }
    }
    if (tid < VV) smarg[tid] = 0.f;
    __syncthreads();

    // ---- Row phase: each warp handles 4 rows ----
    for (int q = 0; q < 4; q++) {
        int r = wid * 4 + q;
        int n = m0 + r;
        int w = n * 2 + g;
        const float* grow = gumbels + (size_t)w * VV;
        const float* lrow = EL + r * ELSTR;

        float l[10], sc[10];
#pragma unroll
        for (int i = 0; i < 10; i++) {
            l[i] = lrow[lane + 32 * i];
            sc[i] = l[i] + grow[lane + 32 * i];
        }

        // argmax of logits + gumbels (first occurrence on ties)
        float best = -3.4e38f;
        int bidx = 0;
#pragma unroll
        for (int i = 0; i < 10; i++) {
            int v = lane + 32 * i;
            if (sc[i] > best) { best = sc[i]; bidx = v; }
        }
        for (int o = 16; o; o >>= 1) {
            float ob = __shfl_down_sync(0xffffffffu, best, o);
            int oi   = __shfl_down_sync(0xffffffffu, bidx, o);
            if (ob > best || (ob == best && oi < bidx)) { best = ob; bidx = oi; }
        }
        best = __shfl_sync(0xffffffffu, best, 0);
        bidx = __shfl_sync(0xffffffffu, bidx, 0);

        // second best (excluding bidx)
        float sec = -3.4e38f;
#pragma unroll
        for (int i = 0; i < 10; i++) {
            int v = lane + 32 * i;
            if (v != bidx && sc[i] > sec) sec = sc[i];
        }
        for (int o = 16; o; o >>= 1) sec = fmaxf(sec, __shfl_xor_sync(0xffffffffu, sec, o));

        // near-tie: exact fp32 rescore of candidates within the window
        if (best - sec < RESCORE_GAP) {
            float thr = best - RESCORE_WIN;
            float exbest = -3.4e38f;
            int exidx = VV;
            int col0 = g * VV;
#pragma unroll
            for (int i = 0; i < 10; i++) {
                unsigned mset = __ballot_sync(0xffffffffu, sc[i] >= thr);
                while (mset) {
                    int src = __ffs(mset) - 1;
                    mset &= mset - 1;
                    int v = src + 32 * i;
                    float ex = exact_score(hidden, W, bias, grow, n, col0 + v, v, lane);
                    if (ex > exbest || (ex == exbest && v < exidx)) { exbest = ex; exidx = v; }
                }
            }
            bidx = exidx;
        }

        // softmax(logits) for marginal (no gumbel, no tau)
        float mx = l[0];
#pragma unroll
        for (int i = 1; i < 10; i++) mx = fmaxf(mx, l[i]);
        for (int o = 16; o; o >>= 1) mx = fmaxf(mx, __shfl_xor_sync(0xffffffffu, mx, o));
        float e[10];
        float sum = 0.f;
#pragma unroll
        for (int i = 0; i < 10; i++) { e[i] = __expf(l[i] - mx); sum += e[i]; }
        for (int o = 16; o; o >>= 1) sum += __shfl_xor_sync(0xffffffffu, sum, o);

        if (g_maskf[n] != 0.f) {
            float inv = 1.f / sum;
#pragma unroll
            for (int i = 0; i < 10; i++)
                atomicAdd(&smarg[lane + 32 * i], e[i] * inv);
        }

        // codevector gather: 128 floats = 32 lanes x float4
        const float4* c4 = (const float4*)(cb + (size_t)(g * VV + bidx) * DG);
        float4* o4 = (float4*)(out + (size_t)n * 256 + g * DG);
        o4[lane] = c4[lane];
    }

    __syncthreads();
    if (tid < VV) atomicAdd(&g_marginal[g * VV + tid], smarg[tid]);
}

// ---------------------------------------------------------------------------
// Final: perplexity = sum_g exp(-sum_v p*log(p+eps)), p = marginal/msum
// ---------------------------------------------------------------------------
__global__ void __launch_bounds__(640) final_kernel(float* __restrict__ out, int out_size) {
    int tid = threadIdx.x;
    float msum = g_msum;
    float val = g_marginal[tid] / msum;
    float t = val * logf(val + 1e-7f);

    __shared__ float s[2];
    if (tid < 2) s[tid] = 0.f;
    __syncthreads();

    for (int o = 16; o; o >>= 1) t += __shfl_xor_sync(0xffffffffu, t, o);
    int warpid = tid >> 5;
    if ((tid & 31) == 0) atomicAdd(&s[warpid >= 10 ? 1 : 0], t);
    __syncthreads();

    if (tid == 0) out[out_size - 1] = expf(-s[0]) + expf(-s[1]);
}

// ---------------------------------------------------------------------------
extern "C" void kernel_launch(void* const* d_in, const int* in_sizes, int n_in,
                              void* d_out, int out_size) {
    const float* hidden = (const float*)d_in[0];   // [8,2048,512]
    const void*  mask   = d_in[1];                 // [8,2048]
    const float* W      = (const float*)d_in[2];   // [512,640]
    const float* b      = (const float*)d_in[3];   // [640]
    const float* cb     = (const float*)d_in[4];   // [1,640,128]
    const float* gum    = (const float*)d_in[5];   // [32768,320]
    float* out = (float*)d_out;

    cudaFuncSetAttribute(fused_kernel,
                         cudaFuncAttributeMaxDynamicSharedMemorySize, FUSED_SMEM);

    pre_kernel<<<PRE_GRID, 1024>>>(hidden, W, mask);

    dim3 fgrid(MM / TM, 2);   // (256, 2)
    fused_kernel<<<fgrid, 512, FUSED_SMEM>>>(b, gum, cb, out, hidden, W);

    final_kernel<<<1, 640>>>(out, out_size);
}

// round 9
// speedup vs baseline: 1.0734x; 1.0734x over previous
#include <cuda_runtime.h>
#include <cuda_bf16.h>
#include <cuda_fp16.h>
#include <cstdint>

// Problem constants: B=8, S=2048, H=512, G=2, V=320, D=256
#define MM 16384      // B*S
#define KK 512        // H
#define NN 640        // G*V
#define VV 320
#define DG 128        // D/G

// ---------------------------------------------------------------------------
// Scratch (static device globals: allocation-free)
// ---------------------------------------------------------------------------
__device__ __half g_logh[(size_t)MM * NN];                  // 20 MB fp16 logits
__device__ __nv_bfloat16 g_Ah[(size_t)MM * KK];             // hidden bf16 [M,K]
__device__ __nv_bfloat16 g_Wh[(size_t)NN * KK];             // W bf16 transposed [N,K]
__device__ float g_marginal[NN];
__device__ float g_maskf[MM];
__device__ float g_msum;
__device__ int g_done;                                       // zero-init; reset by last block

__device__ __forceinline__ uint32_t smem_u32(const void* p) {
    uint32_t a;
    asm("{ .reg .u64 t; cvta.to.shared.u64 t, %1; cvt.u32.u64 %0, t; }" : "=r"(a) : "l"(p));
    return a;
}
__device__ __forceinline__ void cp_async16(uint32_t saddr, const void* gaddr) {
    asm volatile("cp.async.cg.shared.global [%0], [%1], 16;" :: "r"(saddr), "l"(gaddr));
}
__device__ __forceinline__ void ldmatrix_x4(uint32_t* r, uint32_t addr) {
    asm volatile("ldmatrix.sync.aligned.m8n8.x4.shared.b16 {%0,%1,%2,%3}, [%4];"
                 : "=r"(r[0]), "=r"(r[1]), "=r"(r[2]), "=r"(r[3]) : "r"(addr));
}
__device__ __forceinline__ void mma16816(float* c, const uint32_t* a, uint32_t b0, uint32_t b1) {
    asm volatile("mma.sync.aligned.m16n8k16.row.col.f32.bf16.bf16.f32 "
                 "{%0,%1,%2,%3}, {%4,%5,%6,%7}, {%8,%9}, {%0,%1,%2,%3};"
                 : "+f"(c[0]), "+f"(c[1]), "+f"(c[2]), "+f"(c[3])
                 : "r"(a[0]), "r"(a[1]), "r"(a[2]), "r"(a[3]), "r"(b0), "r"(b1));
}

// ---------------------------------------------------------------------------
// Fused pre-pass (ILP 4):
//   block 0        : init (zero marginal, mask detect/expand/sum)
//   blocks 1..320  : convert+transpose W fp32 [K,N] -> bf16 [N,K]
//   blocks 321..832: convert hidden fp32 -> bf16 (4 x float4 per thread)
// ---------------------------------------------------------------------------
#define WT_BLOCKS 320                 // NN*KK / 1024
#define A4_BLOCKS 512                 // MM*KK/4 / 4096
#define PRE_GRID (1 + WT_BLOCKS + A4_BLOCKS)

__global__ void __launch_bounds__(1024) pre_kernel(const float* __restrict__ A,
                                                   const float* __restrict__ W,
                                                   const void* __restrict__ maskraw) {
    int bx = blockIdx.x;
    int tid = threadIdx.x;

    if (bx == 0) {
        if (tid < NN) g_marginal[tid] = 0.f;

        __shared__ int isU8;
        if (tid == 0) isU8 = 0;
        __syncthreads();

        const unsigned char* mb = (const unsigned char*)maskraw;
        int any = 0;
        for (int i = tid; i < MM; i += 1024)
            if ((i & 3) && mb[i]) any = 1;
        if (any) isU8 = 1;
        __syncthreads();

        bool u8 = (isU8 != 0);
        const int* mi = (const int*)maskraw;
        float local = 0.f;
        for (int i = tid; i < MM; i += 1024) {
            bool on = u8 ? (mb[i] != 0) : (mi[i] != 0);
            float v = on ? 1.f : 0.f;
            g_maskf[i] = v;
            local += v;
        }
        __shared__ float red[32];
        for (int o = 16; o; o >>= 1) local += __shfl_xor_sync(0xffffffffu, local, o);
        if ((tid & 31) == 0) red[tid >> 5] = local;
        __syncthreads();
        if (tid < 32) {
            float s = red[tid];
            for (int o = 16; o; o >>= 1) s += __shfl_xor_sync(0xffffffffu, s, o);
            if (tid == 0) g_msum = s;
        }
        return;
    }

    if (bx <= WT_BLOCKS) {
        // W transpose-convert: [K,N] fp32 -> [N,K] bf16
        int idx = (bx - 1) * 1024 + tid;          // over N*K
        int n = idx / KK, k = idx % KK;
        g_Wh[idx] = __float2bfloat16(W[(size_t)k * NN + n]);
    } else {
        // A convert, 4 float4s per thread
        size_t base = (size_t)(bx - 1 - WT_BLOCKS) * 4096 + tid;
#pragma unroll
        for (int u = 0; u < 4; u++) {
            size_t i4 = base + u * 1024;
            float4 v = ((const float4*)A)[i4];
            __nv_bfloat162 h0, h1;
            h0.x = __float2bfloat16(v.x); h0.y = __float2bfloat16(v.y);
            h1.x = __float2bfloat16(v.z); h1.y = __float2bfloat16(v.w);
            ((uint2*)g_Ah)[i4] = make_uint2(*(uint32_t*)&h0, *(uint32_t*)&h1);
        }
    }
}

// ---------------------------------------------------------------------------
// mma.sync bf16 GEMM (R6 mainloop): logits[M,N] = A @ W + bias, fp16 store.
// CTA 128x128, 8 warps (64x32 each), BK=64, 3-stage cp.async ring.
// ---------------------------------------------------------------------------
#define BM 128
#define BN 128
#define BKC 64
#define SSTR 72
#define ROWB (SSTR * 2)               // 144 bytes per smem row
#define NCHUNK 8
#define STAGES 3
#define AB_OFF (BM * ROWB)            // 18432
#define STAGE_BYTES (2 * BM * ROWB)   // 36864
#define GEMM_SMEM (STAGES * STAGE_BYTES)  // 110592

__global__ void __launch_bounds__(256, 2) mma_gemm_kernel(const float* __restrict__ bias) {
    extern __shared__ char smem[];
    uint32_t sbase = smem_u32(smem);

    int tid = threadIdx.x;
    int lane = tid & 31;
    int wid = tid >> 5;
    int wr = wid >> 2;
    int wc = wid & 3;
    int m0 = blockIdx.y * BM;
    int n0 = blockIdx.x * BN;

    float acc[4][4][4];
#pragma unroll
    for (int i = 0; i < 4; i++)
#pragma unroll
        for (int j = 0; j < 4; j++)
#pragma unroll
            for (int r = 0; r < 4; r++) acc[i][j][r] = 0.f;

    int rowA = tid >> 3, seg = tid & 7;

#define LOAD_CHUNK(kc, st) do {                                               \
        int koff = (kc) * BKC;                                                \
        uint32_t sb = sbase + (st) * STAGE_BYTES;                             \
        _Pragma("unroll")                                                     \
        for (int p = 0; p < 4; p++) {                                         \
            int r = rowA + 32 * p;                                            \
            cp_async16(sb + r * ROWB + seg * 16,                              \
                       g_Ah + (size_t)(m0 + r) * KK + koff + seg * 8);        \
            cp_async16(sb + AB_OFF + r * ROWB + seg * 16,                     \
                       g_Wh + (size_t)(n0 + r) * KK + koff + seg * 8);        \
        }                                                                     \
    } while (0)

    LOAD_CHUNK(0, 0); asm volatile("cp.async.commit_group;");
    LOAD_CHUNK(1, 1); asm volatile("cp.async.commit_group;");

    uint32_t aoff = (uint32_t)((wr * 64 + (lane & 15)) * ROWB + (lane >> 4) * 16);
    uint32_t boff = (uint32_t)(AB_OFF + (wc * 32 + (lane & 7) + ((lane >> 4) & 1) * 8) * ROWB
                               + ((lane >> 3) & 1) * 16);

    for (int kc = 0; kc < NCHUNK; kc++) {
        asm volatile("cp.async.wait_group 1;");
        __syncthreads();

        if (kc + 2 < NCHUNK) LOAD_CHUNK(kc + 2, (kc + 2) % 3);
        asm volatile("cp.async.commit_group;");

        uint32_t stb = sbase + (kc % 3) * STAGE_BYTES;
        uint32_t aBase = stb + aoff;
        uint32_t bBase = stb + boff;
#pragma unroll
        for (int kk = 0; kk < 4; kk++) {
            uint32_t kb = kk * 32;
            uint32_t afr[4][4], bfr[2][4];
#pragma unroll
            for (int mi = 0; mi < 4; mi++)
                ldmatrix_x4(afr[mi], aBase + mi * 16 * ROWB + kb);
#pragma unroll
            for (int nj = 0; nj < 2; nj++)
                ldmatrix_x4(bfr[nj], bBase + nj * 16 * ROWB + kb);
#pragma unroll
            for (int mi = 0; mi < 4; mi++)
#pragma unroll
                for (int ni = 0; ni < 4; ni++) {
                    uint32_t b0 = bfr[ni >> 1][(ni & 1) * 2];
                    uint32_t b1 = bfr[ni >> 1][(ni & 1) * 2 + 1];
                    mma16816(acc[mi][ni], afr[mi], b0, b1);
                }
        }
    }

    // Epilogue: bias add + fp16 store
    int l4 = lane >> 2, l2 = (lane & 3) * 2;
    float2 bb[4];
#pragma unroll
    for (int ni = 0; ni < 4; ni++) {
        int col = n0 + wc * 32 + ni * 8 + l2;
        bb[ni].x = __ldg(&bias[col]);
        bb[ni].y = __ldg(&bias[col + 1]);
    }
#pragma unroll
    for (int mi = 0; mi < 4; mi++) {
        int row = m0 + wr * 64 + mi * 16 + l4;
#pragma unroll
        for (int ni = 0; ni < 4; ni++) {
            int col = n0 + wc * 32 + ni * 8 + l2;
            __half2 h0 = __floats2half2_rn(acc[mi][ni][0] + bb[ni].x, acc[mi][ni][1] + bb[ni].y);
            __half2 h1 = __floats2half2_rn(acc[mi][ni][2] + bb[ni].x, acc[mi][ni][3] + bb[ni].y);
            *(__half2*)&g_logh[(size_t)row * NN + col] = h0;
            *(__half2*)&g_logh[(size_t)(row + 8) * NN + col] = h1;
        }
    }
}

// ---------------------------------------------------------------------------
// Exact fp32 rescore of one candidate column (warp-cooperative)
// ---------------------------------------------------------------------------
__device__ __forceinline__ float exact_score(const float* __restrict__ hidden,
                                             const float* __restrict__ W,
                                             const float* __restrict__ bias,
                                             const float* __restrict__ grow,
                                             int n, int col, int v, int lane) {
    const float* hrow = hidden + (size_t)n * KK;
    float s = 0.f;
#pragma unroll 4
    for (int j = lane; j < KK; j += 32)
        s = fmaf(hrow[j], W[(size_t)j * NN + col], s);
    for (int o = 16; o; o >>= 1) s += __shfl_xor_sync(0xffffffffu, s, o);
    return s + bias[col] + grow[v];
}

// ---------------------------------------------------------------------------
// Row kernel (+ merged perplexity finalization in the last block).
// Warp per (n, g). v-mapping: i -> v = 2*(lane + 32*(i/2)) + (i&1).
// ---------------------------------------------------------------------------
#define RESCORE_GAP  3.0e-2f
#define RESCORE_WIN  3.4e-2f
#define ROW_GRID 1024

__global__ void __launch_bounds__(1024) row_kernel(const float* __restrict__ gumbels,
                                                   const float* __restrict__ cb,
                                                   float* __restrict__ out,
                                                   const float* __restrict__ hidden,
                                                   const float* __restrict__ W,
                                                   const float* __restrict__ bias,
                                                   int out_size) {
    __shared__ float smarg[NN];
    int tid = threadIdx.x;
    if (tid < NN) smarg[tid] = 0.f;
    __syncthreads();

    int warpid = tid >> 5;
    int lane = tid & 31;
    int w = blockIdx.x * 32 + warpid;   // flat row index n*G + g
    int n = w >> 1;
    int g = w & 1;

    const __half2* lrow2 = (const __half2*)(g_logh + (size_t)n * NN + g * VV);
    const float* grow = gumbels + (size_t)w * VV;
    const float2* grow2 = (const float2*)grow;

    float l[10], sc[10];
#pragma unroll
    for (int j = 0; j < 5; j++) {
        float2 lf = __half22float2(lrow2[lane + 32 * j]);
        float2 gg = grow2[lane + 32 * j];
        l[2 * j] = lf.x;     l[2 * j + 1] = lf.y;
        sc[2 * j] = lf.x + gg.x;
        sc[2 * j + 1] = lf.y + gg.y;
    }
#define VMAP(i) (2 * (lane + 32 * ((i) >> 1)) + ((i) & 1))

    // argmax of logits + gumbels
    float best = -3.4e38f;
    int bidx = 0;
#pragma unroll
    for (int i = 0; i < 10; i++) {
        int v = VMAP(i);
        if (sc[i] > best || (sc[i] == best && v < bidx)) { best = sc[i]; bidx = v; }
    }
    for (int o = 16; o; o >>= 1) {
        float ob = __shfl_down_sync(0xffffffffu, best, o);
        int oi   = __shfl_down_sync(0xffffffffu, bidx, o);
        if (ob > best || (ob == best && oi < bidx)) { best = ob; bidx = oi; }
    }
    best = __shfl_sync(0xffffffffu, best, 0);
    bidx = __shfl_sync(0xffffffffu, bidx, 0);

    // second best (excluding bidx)
    float sec = -3.4e38f;
#pragma unroll
    for (int i = 0; i < 10; i++) {
        int v = VMAP(i);
        if (v != bidx && sc[i] > sec) sec = sc[i];
    }
    for (int o = 16; o; o >>= 1) sec = fmaxf(sec, __shfl_xor_sync(0xffffffffu, sec, o));

    // near-tie: exact fp32 rescore of candidates within the window
    if (best - sec < RESCORE_GAP) {
        float thr = best - RESCORE_WIN;
        float exbest = -3.4e38f;
        int exidx = VV;
        int col0 = g * VV;
#pragma unroll
        for (int i = 0; i < 10; i++) {
            unsigned mset = __ballot_sync(0xffffffffu, sc[i] >= thr);
            while (mset) {
                int src = __ffs(mset) - 1;
                mset &= mset - 1;
                int v = 2 * (src + 32 * (i >> 1)) + (i & 1);
                float ex = exact_score(hidden, W, bias, grow, n, col0 + v, v, lane);
                if (ex > exbest || (ex == exbest && v < exidx)) { exbest = ex; exidx = v; }
            }
        }
        bidx = exidx;
    }

    // softmax(logits) for marginal
    float mx = l[0];
#pragma unroll
    for (int i = 1; i < 10; i++) mx = fmaxf(mx, l[i]);
    for (int o = 16; o; o >>= 1) mx = fmaxf(mx, __shfl_xor_sync(0xffffffffu, mx, o));
    float e[10];
    float sum = 0.f;
#pragma unroll
    for (int i = 0; i < 10; i++) { e[i] = __expf(l[i] - mx); sum += e[i]; }
    for (int o = 16; o; o >>= 1) sum += __shfl_xor_sync(0xffffffffu, sum, o);

    if (g_maskf[n] != 0.f) {
        float inv = 1.f / sum;
#pragma unroll
        for (int i = 0; i < 10; i++)
            atomicAdd(&smarg[g * VV + VMAP(i)], e[i] * inv);
    }

    // codevector gather
    const float4* c4 = (const float4*)(cb + (size_t)(g * VV + bidx) * DG);
    float4* o4 = (float4*)(out + (size_t)n * 256 + g * DG);
    o4[lane] = c4[lane];

    __syncthreads();
    if (tid < NN) atomicAdd(&g_marginal[tid], smarg[tid]);

    // ---- merged finalization: last block computes perplexity ----
    __shared__ int amLast;
    __threadfence();
    __syncthreads();
    if (tid == 0) amLast = (atomicAdd(&g_done, 1) == ROW_GRID - 1);
    __syncthreads();
    if (amLast) {
        __threadfence();   // acquire marginal written by all blocks
        __shared__ float s2[2];
        if (tid < 2) s2[tid] = 0.f;
        __syncthreads();
        if (tid < NN) {
            float val = g_marginal[tid] / g_msum;
            float t = val * logf(val + 1e-7f);
            for (int o = 16; o; o >>= 1) t += __shfl_xor_sync(0xffffffffu, t, o);
            if ((tid & 31) == 0) atomicAdd(&s2[(tid >> 5) >= 10 ? 1 : 0], t);
        }
        __syncthreads();
        if (tid == 0) {
            out[out_size - 1] = expf(-s2[0]) + expf(-s2[1]);
            g_done = 0;   // reset for next graph replay
        }
    }
}

// ---------------------------------------------------------------------------
extern "C" void kernel_launch(void* const* d_in, const int* in_sizes, int n_in,
                              void* d_out, int out_size) {
    const float* hidden = (const float*)d_in[0];   // [8,2048,512]
    const void*  mask   = d_in[1];                 // [8,2048]
    const float* W      = (const float*)d_in[2];   // [512,640]
    const float* b      = (const float*)d_in[3];   // [640]
    const float* cb     = (const float*)d_in[4];   // [1,640,128]
    const float* gum    = (const float*)d_in[5];   // [32768,320]
    float* out = (float*)d_out;

    cudaFuncSetAttribute(mma_gemm_kernel,
                         cudaFuncAttributeMaxDynamicSharedMemorySize, GEMM_SMEM);

    pre_kernel<<<PRE_GRID, 1024>>>(hidden, W, mask);

    dim3 ggrid(NN / BN, MM / BM);   // (5, 128)
    mma_gemm_kernel<<<ggrid, 256, GEMM_SMEM>>>(b);

    row_kernel<<<ROW_GRID, 1024>>>(gum, cb, out, hidden, W, b, out_size);
}

// round 11
// speedup vs baseline: 1.1243x; 1.0474x over previous
#include <cuda_runtime.h>
#include <cuda_bf16.h>
#include <cuda_fp16.h>
#include <cstdint>

// Problem constants: B=8, S=2048, H=512, G=2, V=320, D=256
#define MM 16384      // B*S
#define KK 512        // H
#define NN 640        // G*V
#define VV 320
#define DG 128        // D/G

// ---------------------------------------------------------------------------
// Scratch (static device globals: allocation-free)
// ---------------------------------------------------------------------------
__device__ __half g_logh[(size_t)MM * NN];                  // 20 MB fp16 logits
__device__ __nv_bfloat16 g_Ah[(size_t)MM * KK];             // hidden bf16 [M,K]
__device__ __nv_bfloat16 g_Wb[(size_t)KK * NN];             // W bf16 [K,N]
__device__ float g_marginal[NN];
__device__ float g_maskf[MM];
__device__ float g_msum;
__device__ int g_done;                                       // zero-init; reset by last block

__device__ __forceinline__ uint32_t smem_u32(const void* p) {
    uint32_t a;
    asm("{ .reg .u64 t; cvta.to.shared.u64 t, %1; cvt.u32.u64 %0, t; }" : "=r"(a) : "l"(p));
    return a;
}
__device__ __forceinline__ void cp_async16(uint32_t saddr, const void* gaddr) {
    asm volatile("cp.async.cg.shared.global [%0], [%1], 16;" :: "r"(saddr), "l"(gaddr));
}
__device__ __forceinline__ void ldmatrix_x4(uint32_t* r, uint32_t addr) {
    asm volatile("ldmatrix.sync.aligned.m8n8.x4.shared.b16 {%0,%1,%2,%3}, [%4];"
                 : "=r"(r[0]), "=r"(r[1]), "=r"(r[2]), "=r"(r[3]) : "r"(addr));
}
__device__ __forceinline__ void ldmatrix_x4_trans(uint32_t* r, uint32_t addr) {
    asm volatile("ldmatrix.sync.aligned.m8n8.x4.trans.shared.b16 {%0,%1,%2,%3}, [%4];"
                 : "=r"(r[0]), "=r"(r[1]), "=r"(r[2]), "=r"(r[3]) : "r"(addr));
}
__device__ __forceinline__ void mma16816(float* c, const uint32_t* a, uint32_t b0, uint32_t b1) {
    asm volatile("mma.sync.aligned.m16n8k16.row.col.f32.bf16.bf16.f32 "
                 "{%0,%1,%2,%3}, {%4,%5,%6,%7}, {%8,%9}, {%0,%1,%2,%3};"
                 : "+f"(c[0]), "+f"(c[1]), "+f"(c[2]), "+f"(c[3])
                 : "r"(a[0]), "r"(a[1]), "r"(a[2]), "r"(a[3]), "r"(b0), "r"(b1));
}

// ---------------------------------------------------------------------------
// Fused pre-pass:
//   block 0         : init (zero marginal, mask detect/expand/sum)
//   blocks 1..80    : convert W fp32 [K,N] -> bf16 [K,N] (float4, coalesced)
//   blocks 81..2128 : convert hidden fp32 -> bf16 (1 float4 per thread)
// ---------------------------------------------------------------------------
#define W4_BLOCKS 80                  // NN*KK/4 / 1024
#define A4_BLOCKS 2048                // MM*KK/4 / 1024
#define PRE_GRID (1 + W4_BLOCKS + A4_BLOCKS)

__global__ void __launch_bounds__(1024) pre_kernel(const float* __restrict__ A,
                                                   const float* __restrict__ W,
                                                   const void* __restrict__ maskraw) {
    int bx = blockIdx.x;
    int tid = threadIdx.x;

    if (bx == 0) {
        if (tid < NN) g_marginal[tid] = 0.f;

        __shared__ int isU8;
        if (tid == 0) isU8 = 0;
        __syncthreads();

        const unsigned char* mb = (const unsigned char*)maskraw;
        int any = 0;
        for (int i = tid; i < MM; i += 1024)
            if ((i & 3) && mb[i]) any = 1;
        if (any) isU8 = 1;
        __syncthreads();

        bool u8 = (isU8 != 0);
        const int* mi = (const int*)maskraw;
        float local = 0.f;
        for (int i = tid; i < MM; i += 1024) {
            bool on = u8 ? (mb[i] != 0) : (mi[i] != 0);
            float v = on ? 1.f : 0.f;
            g_maskf[i] = v;
            local += v;
        }
        __shared__ float red[32];
        for (int o = 16; o; o >>= 1) local += __shfl_xor_sync(0xffffffffu, local, o);
        if ((tid & 31) == 0) red[tid >> 5] = local;
        __syncthreads();
        if (tid < 32) {
            float s = red[tid];
            for (int o = 16; o; o >>= 1) s += __shfl_xor_sync(0xffffffffu, s, o);
            if (tid == 0) g_msum = s;
        }
        return;
    }

    if (bx <= W4_BLOCKS) {
        size_t i4 = (size_t)(bx - 1) * 1024 + tid;             // over NN*KK/4
        float4 v = ((const float4*)W)[i4];
        __nv_bfloat162 h0, h1;
        h0.x = __float2bfloat16(v.x); h0.y = __float2bfloat16(v.y);
        h1.x = __float2bfloat16(v.z); h1.y = __float2bfloat16(v.w);
        ((uint2*)g_Wb)[i4] = make_uint2(*(uint32_t*)&h0, *(uint32_t*)&h1);
    } else {
        size_t i4 = (size_t)(bx - 1 - W4_BLOCKS) * 1024 + tid; // over MM*KK/4
        float4 v = ((const float4*)A)[i4];
        __nv_bfloat162 h0, h1;
        h0.x = __float2bfloat16(v.x); h0.y = __float2bfloat16(v.y);
        h1.x = __float2bfloat16(v.z); h1.y = __float2bfloat16(v.w);
        ((uint2*)g_Ah)[i4] = make_uint2(*(uint32_t*)&h0, *(uint32_t*)&h1);
    }
}

// ---------------------------------------------------------------------------
// mma.sync bf16 GEMM: logits[M,N] = A @ W + bias, fp16 store.
// CTA 128x128, 8 warps (64x32 each), BK=64, 3-stage cp.async ring.
// A: m-major smem (pitch 144B), non-trans ldsm. B: k-major smem (pitch 272B),
// trans ldsm straight from the [K,N] bf16 copy of W (no transpose pre-pass).
// ---------------------------------------------------------------------------
#define BM 128
#define BN 128
#define BKC 64
#define AROWB 144                     // 64 bf16 + pad
#define BROWB 272                     // 128 bf16 + pad
#define NCHUNK 8
#define STAGES 3
#define AB_OFF (BM * AROWB)           // 18432
#define STAGE_BYTES (AB_OFF + BKC * BROWB)   // 18432 + 17408 = 35840
#define GEMM_SMEM (STAGES * STAGE_BYTES)     // 107520

__global__ void __launch_bounds__(256, 2) mma_gemm_kernel(const float* __restrict__ bias) {
    extern __shared__ char smem[];
    uint32_t sbase = smem_u32(smem);

    int tid = threadIdx.x;
    int lane = tid & 31;
    int wid = tid >> 5;
    int wr = wid >> 2;
    int wc = wid & 3;
    int m0 = blockIdx.y * BM;
    int n0 = blockIdx.x * BN;

    float acc[4][4][4];
#pragma unroll
    for (int i = 0; i < 4; i++)
#pragma unroll
        for (int j = 0; j < 4; j++)
#pragma unroll
            for (int r = 0; r < 4; r++) acc[i][j][r] = 0.f;

    int rowA = tid >> 3, segA = tid & 7;   // A: 1024 segs of 16B (4 iters)
    int rowB = tid >> 4, segB = tid & 15;  // B: 1024 segs of 16B (4 iters)

#define LOAD_CHUNK(kc, st) do {                                               \
        int koff = (kc) * BKC;                                                \
        uint32_t sb = sbase + (st) * STAGE_BYTES;                             \
        _Pragma("unroll")                                                     \
        for (int p = 0; p < 4; p++) {                                         \
            int r = rowA + 32 * p;                                            \
            cp_async16(sb + r * AROWB + segA * 16,                            \
                       g_Ah + (size_t)(m0 + r) * KK + koff + segA * 8);       \
        }                                                                     \
        _Pragma("unroll")                                                     \
        for (int p = 0; p < 4; p++) {                                         \
            int r = rowB + 16 * p;                                            \
            cp_async16(sb + AB_OFF + r * BROWB + segB * 16,                   \
                       g_Wb + (size_t)(koff + r) * NN + n0 + segB * 8);       \
        }                                                                     \
    } while (0)

    LOAD_CHUNK(0, 0); asm volatile("cp.async.commit_group;");
    LOAD_CHUNK(1, 1); asm volatile("cp.async.commit_group;");

    uint32_t aoff = (uint32_t)((wr * 64 + (lane & 15)) * AROWB + (lane >> 4) * 16);
    uint32_t boff = (uint32_t)(AB_OFF + ((lane & 7) + ((lane >> 3) & 1) * 8) * BROWB
                               + (wc * 32 + (lane >> 4) * 8) * 2);

    for (int kc = 0; kc < NCHUNK; kc++) {
        asm volatile("cp.async.wait_group 1;");
        __syncthreads();

        if (kc + 2 < NCHUNK) LOAD_CHUNK(kc + 2, (kc + 2) % 3);
        asm volatile("cp.async.commit_group;");

        uint32_t stb = sbase + (kc % 3) * STAGE_BYTES;
        uint32_t aBase = stb + aoff;
        uint32_t bBase = stb + boff;
#pragma unroll
        for (int kk = 0; kk < 4; kk++) {
            uint32_t afr[4][4], bfr[2][4];
#pragma unroll
            for (int mi = 0; mi < 4; mi++)
                ldmatrix_x4(afr[mi], aBase + mi * 16 * AROWB + kk * 32);
#pragma unroll
            for (int nj = 0; nj < 2; nj++)
                ldmatrix_x4_trans(bfr[nj], bBase + kk * 16 * BROWB + nj * 32);
#pragma unroll
            for (int mi = 0; mi < 4; mi++)
#pragma unroll
                for (int ni = 0; ni < 4; ni++) {
                    uint32_t b0 = bfr[ni >> 1][(ni & 1) * 2];
                    uint32_t b1 = bfr[ni >> 1][(ni & 1) * 2 + 1];
                    mma16816(acc[mi][ni], afr[mi], b0, b1);
                }
        }
    }

    // Epilogue: bias add + fp16 store
    int l4 = lane >> 2, l2 = (lane & 3) * 2;
    float2 bb[4];
#pragma unroll
    for (int ni = 0; ni < 4; ni++) {
        int col = n0 + wc * 32 + ni * 8 + l2;
        bb[ni].x = __ldg(&bias[col]);
        bb[ni].y = __ldg(&bias[col + 1]);
    }
#pragma unroll
    for (int mi = 0; mi < 4; mi++) {
        int row = m0 + wr * 64 + mi * 16 + l4;
#pragma unroll
        for (int ni = 0; ni < 4; ni++) {
            int col = n0 + wc * 32 + ni * 8 + l2;
            __half2 h0 = __floats2half2_rn(acc[mi][ni][0] + bb[ni].x, acc[mi][ni][1] + bb[ni].y);
            __half2 h1 = __floats2half2_rn(acc[mi][ni][2] + bb[ni].x, acc[mi][ni][3] + bb[ni].y);
            *(__half2*)&g_logh[(size_t)row * NN + col] = h0;
            *(__half2*)&g_logh[(size_t)(row + 8) * NN + col] = h1;
        }
    }
}

// ---------------------------------------------------------------------------
// Exact fp32 rescore of one candidate column (warp-cooperative)
// ---------------------------------------------------------------------------
__device__ __forceinline__ float exact_score(const float* __restrict__ hidden,
                                             const float* __restrict__ W,
                                             const float* __restrict__ bias,
                                             const float* __restrict__ grow,
                                             int n, int col, int v, int lane) {
    const float* hrow = hidden + (size_t)n * KK;
    float s = 0.f;
#pragma unroll 4
    for (int j = lane; j < KK; j += 32)
        s = fmaf(hrow[j], W[(size_t)j * NN + col], s);
    for (int o = 16; o; o >>= 1) s += __shfl_xor_sync(0xffffffffu, s, o);
    return s + bias[col] + grow[v];
}

// ---------------------------------------------------------------------------
// Row kernel: warp handles 4 rows of one group; marginal accumulated in
// registers across rows, then 10 smem atomics per warp. Last block computes
// perplexity. v-mapping: i -> v = 2*(lane + 32*(i/2)) + (i&1).
// ---------------------------------------------------------------------------
#define RESCORE_GAP  3.0e-2f
#define RESCORE_WIN  3.4e-2f
#define ROW_GRID 512
#define ROW_THREADS 512

__global__ void __launch_bounds__(ROW_THREADS) row_kernel(const float* __restrict__ gumbels,
                                                          const float* __restrict__ cb,
                                                          float* __restrict__ out,
                                                          const float* __restrict__ hidden,
                                                          const float* __restrict__ W,
                                                          const float* __restrict__ bias,
                                                          int out_size) {
    __shared__ float smarg[NN];
    int tid = threadIdx.x;
    for (int i = tid; i < NN; i += ROW_THREADS) smarg[i] = 0.f;
    __syncthreads();

    int warpid = tid >> 5;              // 0..15
    int lane = tid & 31;
    int g = warpid & 1;
    int nbase = (blockIdx.x * 8 + (warpid >> 1)) * 4;   // 512*8*4 = 16384 rows

#define VMAP(i) (2 * (lane + 32 * ((i) >> 1)) + ((i) & 1))

    float mreg[10];
#pragma unroll
    for (int i = 0; i < 10; i++) mreg[i] = 0.f;

    for (int q = 0; q < 4; q++) {
        int n = nbase + q;
        int w = n * 2 + g;
        const __half2* lrow2 = (const __half2*)(g_logh + (size_t)n * NN + g * VV);
        const float* grow = gumbels + (size_t)w * VV;
        const float2* grow2 = (const float2*)grow;

        float l[10], sc[10];
#pragma unroll
        for (int j = 0; j < 5; j++) {
            float2 lf = __half22float2(lrow2[lane + 32 * j]);
            float2 gg = grow2[lane + 32 * j];
            l[2 * j] = lf.x;     l[2 * j + 1] = lf.y;
            sc[2 * j] = lf.x + gg.x;
            sc[2 * j + 1] = lf.y + gg.y;
        }

        // argmax of logits + gumbels
        float best = -3.4e38f;
        int bidx = 0;
#pragma unroll
        for (int i = 0; i < 10; i++) {
            int v = VMAP(i);
            if (sc[i] > best || (sc[i] == best && v < bidx)) { best = sc[i]; bidx = v; }
        }
        for (int o = 16; o; o >>= 1) {
            float ob = __shfl_down_sync(0xffffffffu, best, o);
            int oi   = __shfl_down_sync(0xffffffffu, bidx, o);
            if (ob > best || (ob == best && oi < bidx)) { best = ob; bidx = oi; }
        }
        best = __shfl_sync(0xffffffffu, best, 0);
        bidx = __shfl_sync(0xffffffffu, bidx, 0);

        // second best (excluding bidx)
        float sec = -3.4e38f;
#pragma unroll
        for (int i = 0; i < 10; i++) {
            int v = VMAP(i);
            if (v != bidx && sc[i] > sec) sec = sc[i];
        }
        for (int o = 16; o; o >>= 1) sec = fmaxf(sec, __shfl_xor_sync(0xffffffffu, sec, o));

        // near-tie: exact fp32 rescore of candidates within the window
        if (best - sec < RESCORE_GAP) {
            float thr = best - RESCORE_WIN;
            float exbest = -3.4e38f;
            int exidx = VV;
            int col0 = g * VV;
#pragma unroll
            for (int i = 0; i < 10; i++) {
                unsigned mset = __ballot_sync(0xffffffffu, sc[i] >= thr);
                while (mset) {
                    int src = __ffs(mset) - 1;
                    mset &= mset - 1;
                    int v = 2 * (src + 32 * (i >> 1)) + (i & 1);
                    float ex = exact_score(hidden, W, bias, grow, n, col0 + v, v, lane);
                    if (ex > exbest || (ex == exbest && v < exidx)) { exbest = ex; exidx = v; }
                }
            }
            bidx = exidx;
        }

        // softmax(logits) for marginal
        float mx = l[0];
#pragma unroll
        for (int i = 1; i < 10; i++) mx = fmaxf(mx, l[i]);
        for (int o = 16; o; o >>= 1) mx = fmaxf(mx, __shfl_xor_sync(0xffffffffu, mx, o));
        float e[10];
        float sum = 0.f;
#pragma unroll
        for (int i = 0; i < 10; i++) { e[i] = __expf(l[i] - mx); sum += e[i]; }
        for (int o = 16; o; o >>= 1) sum += __shfl_xor_sync(0xffffffffu, sum, o);

        if (g_maskf[n] != 0.f) {
            float inv = 1.f / sum;
#pragma unroll
            for (int i = 0; i < 10; i++) mreg[i] = fmaf(e[i], inv, mreg[i]);
        }

        // codevector gather
        const float4* c4 = (const float4*)(cb + (size_t)(g * VV + bidx) * DG);
        float4* o4 = (float4*)(out + (size_t)n * 256 + g * DG);
        o4[lane] = c4[lane];
    }

    // one batch of smem atomics per warp (4 rows folded in registers)
#pragma unroll
    for (int i = 0; i < 10; i++)
        atomicAdd(&smarg[g * VV + VMAP(i)], mreg[i]);

    __syncthreads();
    for (int i = tid; i < NN; i += ROW_THREADS) atomicAdd(&g_marginal[i], smarg[i]);

    // ---- merged finalization: last block computes perplexity ----
    __shared__ int amLast;
    __threadfence();
    __syncthreads();
    if (tid == 0) amLast = (atomicAdd(&g_done, 1) == ROW_GRID - 1);
    __syncthreads();
    if (amLast) {
        __threadfence();   // acquire marginal written by all blocks
        __shared__ float s2[2];
        if (tid < 2) s2[tid] = 0.f;
        __syncthreads();
        float t0 = 0.f, t1 = 0.f;
        for (int i = tid; i < NN; i += ROW_THREADS) {
            float val = g_marginal[i] / g_msum;
            float t = val * logf(val + 1e-7f);
            if (i < VV) t0 += t; else t1 += t;
        }
        for (int o = 16; o; o >>= 1) {
            t0 += __shfl_xor_sync(0xffffffffu, t0, o);
            t1 += __shfl_xor_sync(0xffffffffu, t1, o);
        }
        if (lane == 0) { atomicAdd(&s2[0], t0); atomicAdd(&s2[1], t1); }
        __syncthreads();
        if (tid == 0) {
            out[out_size - 1] = expf(-s2[0]) + expf(-s2[1]);
            g_done = 0;   // reset for next graph replay
        }
    }
}

// ---------------------------------------------------------------------------
extern "C" void kernel_launch(void* const* d_in, const int* in_sizes, int n_in,
                              void* d_out, int out_size) {
    const float* hidden = (const float*)d_in[0];   // [8,2048,512]
    const void*  mask   = d_in[1];                 // [8,2048]
    const float* W      = (const float*)d_in[2];   // [512,640]
    const float* b      = (const float*)d_in[3];   // [640]
    const float* cb     = (const float*)d_in[4];   // [1,640,128]
    const float* gum    = (const float*)d_in[5];   // [32768,320]
    float* out = (float*)d_out;

    cudaFuncSetAttribute(mma_gemm_kernel,
                         cudaFuncAttributeMaxDynamicSharedMemorySize, GEMM_SMEM);

    pre_kernel<<<PRE_GRID, 1024>>>(hidden, W, mask);

    dim3 ggrid(NN / BN, MM / BM);   // (5, 128)
    mma_gemm_kernel<<<ggrid, 256, GEMM_SMEM>>>(b);

    row_kernel<<<ROW_GRID, ROW_THREADS>>>(gum, cb, out, hidden, W, b, out_size);
}